// round 14
// baseline (speedup 1.0000x reference)
#include <cuda_runtime.h>

#define BB 256
#define TT 200
#define QQ 1024
#define NROWS (BB * (TT - 1))     // 50944 rows (t = 1..199)
#define WPC   8                   // warps per CTA
#define NCTA  (NROWS / WPC)       // 6368 CTAs, one row per warp, multi-wave

__device__ float        g_partials[NCTA];
__device__ unsigned int g_done = 0;   // reset by last CTA each run (replay-safe)

// Scan one 4KB half-row (256 float4) with a full warp: 8 independent 16B
// streaming loads per lane, locate the unique nonzero (value is exactly 1.0).
// Returns its index in [0,1024) broadcast to all lanes, or -1 if all-zero.
__device__ __forceinline__ int scan_half(const uint4* __restrict__ base, int lane)
{
    uint4 v[8];
    #pragma unroll
    for (int i = 0; i < 8; i++)
        v[i] = __ldcs(base + lane + 32 * i);

    int q = -1;
    #pragma unroll
    for (int i = 0; i < 8; i++) {
        const int b4 = (lane + 32 * i) * 4;
        if      (v[i].x) q = b4 + 0;
        else if (v[i].y) q = b4 + 1;
        else if (v[i].z) q = b4 + 2;
        else if (v[i].w) q = b4 + 3;
    }
    const unsigned bal = __ballot_sync(0xffffffffu, q >= 0);
    if (bal == 0u) return -1;
    return __shfl_sync(0xffffffffu, q, __ffs(bal) - 1);
}

// One row per warp; small CTAs over ~5.4 waves so the hardware work
// distributor absorbs the data-dependent (neg-scan) imbalance.
__global__ __launch_bounds__(256) void loss_kernel(
    const float* __restrict__ pred,
    const float* __restrict__ batch,
    float* __restrict__ out)
{
    const int tid  = threadIdx.x;
    const int lane = tid & 31;
    const int wid  = tid >> 5;
    const int n    = blockIdx.x * WPC + wid;   // row id, always < NROWS

    const int b = n / (TT - 1);
    const int t = n % (TT - 1) + 1;

    const uint4* row = reinterpret_cast<const uint4*>(
        batch + ((size_t)b * TT + t) * (size_t)(2 * QQ));

    // pos half first; its hit encodes a=1. Neg half only on miss (a=0).
    float a = 1.0f;
    int   q = scan_half(row, lane);
    if (q < 0) {
        q = scan_half(row + QQ / 4, lane);
        a = 0.0f;
    }

    __shared__ float s_acc[WPC];
    __shared__ int   s_last;

    if (lane == 0) {
        float c = 0.0f;
        if (q >= 0) {
            // delta value is exactly 1.0 => probs = pred[b, t-1, q]
            const float p = __ldg(&pred[((size_t)b * TT + (t - 1)) * QQ + q]);
            if (p > 0.0f)
                c = (a > 0.5f) ? -logf(p) : -log1pf(-p);
        }
        s_acc[wid] = c;
    }
    __syncthreads();

    if (tid == 0) {
        float partial = 0.0f;
        #pragma unroll
        for (int i = 0; i < WPC; i++) partial += s_acc[i];
        g_partials[blockIdx.x] = partial;
        __threadfence();
        const unsigned old = atomicAdd(&g_done, 1u);
        s_last = (old == NCTA - 1);
    }
    __syncthreads();

    // ---- last CTA: deterministic final reduction + counter reset ----
    if (s_last) {
        if (tid == 0) g_done = 0;
        __threadfence();
        __shared__ float s_red[256];
        float s = 0.0f;
        for (int i = tid; i < NCTA; i += 256) s += g_partials[i];
        s_red[tid] = s;
        __syncthreads();
        #pragma unroll
        for (int o = 128; o > 0; o >>= 1) {
            if (tid < o) s_red[tid] += s_red[tid + o];
            __syncthreads();
        }
        if (tid == 0) out[0] = s_red[0];
    }
}

extern "C" void kernel_launch(void* const* d_in, const int* in_sizes, int n_in,
                              void* d_out, int out_size)
{
    const float* pred  = (const float*)d_in[0];
    const float* batch = (const float*)d_in[1];
    if (n_in >= 2 && in_sizes[0] > in_sizes[1]) {
        const float* tmp = pred; pred = batch; batch = tmp;
    }

    loss_kernel<<<NCTA, 256>>>(pred, batch, (float*)d_out);
}

// round 16
// speedup vs baseline: 1.0297x; 1.0297x over previous
#include <cuda_runtime.h>

#define BB 256
#define TT 200
#define QQ 1024
#define NROWS (BB * (TT - 1))     // 50944 rows (t = 1..199)
#define WPC   8                   // warps per CTA
#define NCTA  (NROWS / WPC)       // 6368 CTAs, one row per warp, multi-wave

__device__ float        g_partials[NCTA];
__device__ unsigned int g_done = 0;   // reset by last CTA each run (replay-safe)

// Scan one 4KB half-row (256 float4) with a full warp: 8 independent 16B
// streaming loads per lane, locate the unique nonzero (value is exactly 1.0).
// Returns its index in [0,1024) broadcast to all lanes, or -1 if all-zero.
__device__ __forceinline__ int scan_half(const uint4* __restrict__ base, int lane)
{
    uint4 v[8];
    #pragma unroll
    for (int i = 0; i < 8; i++)
        v[i] = __ldcs(base + lane + 32 * i);

    int q = -1;
    #pragma unroll
    for (int i = 0; i < 8; i++) {
        const int b4 = (lane + 32 * i) * 4;
        if      (v[i].x) q = b4 + 0;
        else if (v[i].y) q = b4 + 1;
        else if (v[i].z) q = b4 + 2;
        else if (v[i].w) q = b4 + 3;
    }
    const unsigned bal = __ballot_sync(0xffffffffu, q >= 0);
    if (bal == 0u) return -1;
    return __shfl_sync(0xffffffffu, q, __ffs(bal) - 1);
}

// One row per warp; small CTAs over ~5.4 waves so the hardware work
// distributor absorbs the data-dependent (neg-scan) imbalance.
__global__ __launch_bounds__(256) void loss_kernel(
    const float* __restrict__ pred,
    const float* __restrict__ batch,
    float* __restrict__ out)
{
    const int tid  = threadIdx.x;
    const int lane = tid & 31;
    const int wid  = tid >> 5;
    const int n    = blockIdx.x * WPC + wid;   // row id, always < NROWS

    const int b = n / (TT - 1);
    const int t = n % (TT - 1) + 1;

    const uint4* row = reinterpret_cast<const uint4*>(
        batch + ((size_t)b * TT + t) * (size_t)(2 * QQ));

    // pos half first; its hit encodes a=1. Neg half only on miss (a=0).
    float a = 1.0f;
    int   q = scan_half(row, lane);
    if (q < 0) {
        q = scan_half(row + QQ / 4, lane);
        a = 0.0f;
    }

    __shared__ float s_acc[WPC];
    __shared__ int   s_last;

    if (lane == 0) {
        float c = 0.0f;
        if (q >= 0) {
            // delta value is exactly 1.0 => probs = pred[b, t-1, q]
            const float p = __ldg(&pred[((size_t)b * TT + (t - 1)) * QQ + q]);
            if (p > 0.0f)
                c = (a > 0.5f) ? -logf(p) : -log1pf(-p);
        }
        s_acc[wid] = c;
    }
    __syncthreads();

    if (tid == 0) {
        float partial = 0.0f;
        #pragma unroll
        for (int i = 0; i < WPC; i++) partial += s_acc[i];
        g_partials[blockIdx.x] = partial;
        __threadfence();
        const unsigned old = atomicAdd(&g_done, 1u);
        s_last = (old == NCTA - 1);
    }
    __syncthreads();

    // ---- last CTA: deterministic final reduction + counter reset ----
    if (s_last) {
        if (tid == 0) g_done = 0;
        __threadfence();
        __shared__ float s_red[256];
        float s = 0.0f;
        for (int i = tid; i < NCTA; i += 256) s += g_partials[i];
        s_red[tid] = s;
        __syncthreads();
        #pragma unroll
        for (int o = 128; o > 0; o >>= 1) {
            if (tid < o) s_red[tid] += s_red[tid + o];
            __syncthreads();
        }
        if (tid == 0) out[0] = s_red[0];
    }
}

extern "C" void kernel_launch(void* const* d_in, const int* in_sizes, int n_in,
                              void* d_out, int out_size)
{
    const float* pred  = (const float*)d_in[0];
    const float* batch = (const float*)d_in[1];
    if (n_in >= 2 && in_sizes[0] > in_sizes[1]) {
        const float* tmp = pred; pred = batch; batch = tmp;
    }

    loss_kernel<<<NCTA, 256>>>(pred, batch, (float*)d_out);
}